// round 6
// baseline (speedup 1.0000x reference)
#include <cuda_runtime.h>
#include <cstdint>
#include <cstddef>

#define B_TOT 512
#define IC    1152
#define KD    8
#define NC    10
#define DDIM  16
#define CD    160

#define BT      32      // b per block (4 warps x 8)
#define IT      8       // i per block
#define THREADS 128

// W smem layout: [il][c][dq][k][dd-pair]; dq stride 36 words (4 pad)
#define WILS    1440              // 10 * 144
#define W_WORDS (IT * WILS)       // 11520
#define USTR    68
#define U_WORDS (BT * USTR)       // 2176
#define VC_WORDS (BT * CD)        // 5120
#define SMEM_WORDS (W_WORDS + U_WORDS + VC_WORDS)   // 18816 -> 75.3 KB

// ---------------- scratch ---------------------------------------------------
__device__ float g_s[3 * B_TOT * CD];   // s1 | s2 | s3

// ---------------- helpers ---------------------------------------------------
typedef unsigned long long ull;
__device__ __forceinline__ ull pack2(float lo, float hi) {
    ull r; asm("mov.b64 %0, {%1, %2};" : "=l"(r) : "f"(lo), "f"(hi)); return r;
}
__device__ __forceinline__ void unpack2(ull p, float& lo, float& hi) {
    asm("mov.b64 {%0, %1}, %2;" : "=f"(lo), "=f"(hi) : "l"(p));
}
__device__ __forceinline__ ull fma2(ull a, ull b, ull c) {
    ull d; asm("fma.rn.f32x2 %0, %1, %2, %3;" : "=l"(d) : "l"(a), "l"(b), "l"(c)); return d;
}
__device__ __forceinline__ ull add2(ull a, ull b) {
    ull d; asm("add.rn.f32x2 %0, %1, %2;" : "=l"(d) : "l"(a), "l"(b)); return d;
}
__device__ __forceinline__ ull mul2(ull a, ull b) {
    ull d; asm("mul.rn.f32x2 %0, %1, %2;" : "=l"(d) : "l"(a), "l"(b)); return d;
}
__device__ __forceinline__ float ex2a(float x) { float y; asm("ex2.approx.f32 %0, %1;" : "=f"(y) : "f"(x)); return y; }
__device__ __forceinline__ float rcpa(float x) { float y; asm("rcp.approx.f32 %0, %1;" : "=f"(y) : "f"(x)); return y; }

// ---------------- fused pass ------------------------------------------------
// MODE 0: s_out += sum_i u_hat            (coupling = uniform)
// MODE 1: coupling from v1 = squash(0.1*s_in1)
// MODE 2: coupling from v1 + v2 (v2 = squash(s_in2))
template <int MODE>
__global__ void __launch_bounds__(THREADS, 3)
k_pass(const float* __restrict__ u, const float* __restrict__ W,
       const float* __restrict__ s_in1, const float* __restrict__ s_in2,
       float* __restrict__ s_out) {
    extern __shared__ float sm[];
    float* w_s  = sm;
    float* u_s  = sm + W_WORDS;
    float* vc_s = u_s + U_WORDS;

    const int tid = threadIdx.x;
    const int b0  = blockIdx.x * BT;
    const int i0  = blockIdx.y * IT;

    // stage W: global [i][c][d][k] -> smem [il][c][dq=d>>2][k][d&3] (pad 4/dq)
    for (int idx = tid; idx < IT * 1280; idx += THREADS) {
        const int il = idx / 1280, rem = idx - il * 1280;
        const int c = rem >> 7, t = rem & 127;
        const int d = t >> 3, k = t & 7;
        w_s[il * WILS + c * 144 + (d >> 2) * 36 + k * 4 + (d & 3)] =
            W[(size_t)i0 * 1280 + idx];
    }
    // stage u
    for (int idx = tid; idx < BT * IT * KD; idx += THREADS) {
        const int bl = idx / (IT * KD), r = idx - bl * (IT * KD);
        u_s[bl * USTR + r] = u[(size_t)(b0 + bl) * (IC * KD) + i0 * KD + r];
    }
    // stage per-b coupling vectors vc[b][c][d]
    if (MODE >= 1) {
        for (int task = tid; task < BT * NC; task += THREADS) {
            const int bl = task / NC, c = task - bl * NC;
            const float* sp = s_in1 + (size_t)(b0 + bl) * CD + c * DDIM;
            float vc[16]; float n2 = 0.f;
#pragma unroll
            for (int d = 0; d < 16; d++) { vc[d] = sp[d] * 0.1f; n2 += vc[d] * vc[d]; }
            float f = (n2 / (1.f + n2)) / (sqrtf(n2) + 1e-8f);
#pragma unroll
            for (int d = 0; d < 16; d++) vc[d] *= f;
            if (MODE == 2) {
                const float* sq = s_in2 + (size_t)(b0 + bl) * CD + c * DDIM;
                float vb[16]; float m2 = 0.f;
#pragma unroll
                for (int d = 0; d < 16; d++) { vb[d] = sq[d]; m2 += vb[d] * vb[d]; }
                float g = (m2 / (1.f + m2)) / (sqrtf(m2) + 1e-8f);
#pragma unroll
                for (int d = 0; d < 16; d++) vc[d] += g * vb[d];
            }
#pragma unroll
            for (int d = 0; d < 16; d++) vc_s[bl * CD + c * DDIM + d] = vc[d];
        }
    }
    __syncthreads();

    const int w = tid >> 5, lane = tid & 31;
    const int dq = lane >> 3, bo = lane & 7;
    const int bl = w * 8 + bo;

    const float* up  = &u_s[bl * USTR];
    const float* wpq = &w_s[dq * 36];
    const ull*   vcp = (const ull*)&vc_s[bl * CD];   // ull idx: c*8 + dq*2

    ull sacc01[NC], sacc23[NC];
#pragma unroll
    for (int c = 0; c < NC; c++) { sacc01[c] = 0ull; sacc23[c] = 0ull; }

#pragma unroll 1
    for (int il = 0; il < IT; il++) {
        const float4 ua = *(const float4*)(up + il * KD);
        const float4 ub = *(const float4*)(up + il * KD + 4);
        ull ud[8];
        ud[0] = pack2(ua.x, ua.x); ud[1] = pack2(ua.y, ua.y);
        ud[2] = pack2(ua.z, ua.z); ud[3] = pack2(ua.w, ua.w);
        ud[4] = pack2(ub.x, ub.x); ud[5] = pack2(ub.y, ub.y);
        ud[6] = pack2(ub.z, ub.z); ud[7] = pack2(ub.w, ub.w);
        const float* wpi = wpq + il * WILS;

        ull uh01[NC], uh23[NC];
#pragma unroll
        for (int c = 0; c < NC; c++) {
            const ull* wc = (const ull*)(wpi + c * 144);
            ull a01 = 0ull, a23 = 0ull;
#pragma unroll
            for (int k = 0; k < 8; k++) {
                a01 = fma2(wc[k * 2],     ud[k], a01);
                a23 = fma2(wc[k * 2 + 1], ud[k], a23);
            }
            if (MODE == 0) {
                sacc01[c] = add2(sacc01[c], a01);
                sacc23[c] = add2(sacc23[c], a23);
            } else {
                uh01[c] = a01; uh23[c] = a23;
            }
        }
        if (MODE >= 1) {
            float e[NC]; float esum = 0.f;
#pragma unroll
            for (int c = 0; c < NC; c++) {
                ull t = add2(mul2(uh01[c], vcp[c * 8 + dq * 2]),
                             mul2(uh23[c], vcp[c * 8 + dq * 2 + 1]));
                float lo, hi; unpack2(t, lo, hi);
                float lp = lo + hi;
                lp += __shfl_xor_sync(0xffffffffu, lp, 8);
                lp += __shfl_xor_sync(0xffffffffu, lp, 16);
                e[c] = ex2a(lp * 1.4426950408889634f);
                esum += e[c];
            }
            const float r = rcpa(esum);
#pragma unroll
            for (int c = 0; c < NC; c++) {
                const float cw = e[c] * r;
                const ull cwp = pack2(cw, cw);
                sacc01[c] = fma2(uh01[c], cwp, sacc01[c]);
                sacc23[c] = fma2(uh23[c], cwp, sacc23[c]);
            }
        }
    }

    float* so = s_out + (size_t)(b0 + bl) * CD + dq * 4;
#pragma unroll
    for (int c = 0; c < NC; c++) {
        float f0, f1, f2, f3;
        unpack2(sacc01[c], f0, f1); unpack2(sacc23[c], f2, f3);
        atomicAdd(&so[c * DDIM + 0], f0);
        atomicAdd(&so[c * DDIM + 1], f1);
        atomicAdd(&so[c * DDIM + 2], f2);
        atomicAdd(&so[c * DDIM + 3], f3);
    }
}

// ---------------- final squash ----------------------------------------------
__global__ void k_squash(const float* __restrict__ s, float* __restrict__ v) {
    const int idx = blockIdx.x * blockDim.x + threadIdx.x;   // (b, c)
    if (idx >= B_TOT * NC) return;
    float vals[16];
    const float4* s4 = (const float4*)(s + (size_t)idx * 16);
    float n2 = 0.f;
#pragma unroll
    for (int q = 0; q < 4; q++) {
        float4 t = s4[q];
        vals[4*q+0] = t.x; vals[4*q+1] = t.y; vals[4*q+2] = t.z; vals[4*q+3] = t.w;
        n2 += t.x*t.x + t.y*t.y + t.z*t.z + t.w*t.w;
    }
    const float f = (n2 / (1.f + n2)) / (sqrtf(n2) + 1e-8f);
    float4* v4 = (float4*)(v + (size_t)idx * 16);
#pragma unroll
    for (int q = 0; q < 4; q++)
        v4[q] = make_float4(f*vals[4*q], f*vals[4*q+1], f*vals[4*q+2], f*vals[4*q+3]);
}

// ---------------- launch -----------------------------------------------------
extern "C" void kernel_launch(void* const* d_in, const int* in_sizes, int n_in,
                              void* d_out, int out_size) {
    const float* u = (const float*)d_in[0];
    const float* W = (const float*)d_in[1];
    if (n_in >= 2 && in_sizes[0] == IC * CD * KD) {   // swap safety
        const float* t = u; u = W; W = t;
    }

    const int smem_bytes = SMEM_WORDS * (int)sizeof(float);
    cudaFuncSetAttribute(k_pass<0>, cudaFuncAttributeMaxDynamicSharedMemorySize, smem_bytes);
    cudaFuncSetAttribute(k_pass<1>, cudaFuncAttributeMaxDynamicSharedMemorySize, smem_bytes);
    cudaFuncSetAttribute(k_pass<2>, cudaFuncAttributeMaxDynamicSharedMemorySize, smem_bytes);

    void* ps;
    cudaGetSymbolAddress(&ps, g_s);
    float* s1 = (float*)ps;
    float* s2 = s1 + B_TOT * CD;
    float* s3 = s2 + B_TOT * CD;

    cudaMemsetAsync(ps, 0, 3 * B_TOT * CD * sizeof(float), 0);

    const dim3 grid(B_TOT / BT, IC / IT);   // (16, 144)
    // pass 0: s1 = sum_i u_hat
    k_pass<0><<<grid, THREADS, smem_bytes>>>(u, W, nullptr, nullptr, s1);
    // pass 1: coupling from v1 = squash(0.1*s1) -> s2
    k_pass<1><<<grid, THREADS, smem_bytes>>>(u, W, s1, nullptr, s2);
    // pass 2: coupling from v1 + v2 -> s3
    k_pass<2><<<grid, THREADS, smem_bytes>>>(u, W, s1, s2, s3);
    // output = squash(s3)
    const int sq_blocks = (B_TOT * NC + 255) / 256;
    k_squash<<<sq_blocks, 256>>>(s3, (float*)d_out);
}

// round 7
// speedup vs baseline: 1.8883x; 1.8883x over previous
#include <cuda_runtime.h>
#include <cuda_fp16.h>
#include <cstdint>
#include <cstddef>

#define B_TOT 512
#define IC    1152
#define CD    160
#define KD    8
#define NC    10

// ---------------- scratch (device globals; no runtime allocation) ----------
__device__ __half g_uhat[(size_t)B_TOT * IC * CD];   // 188 MB, fp16
__device__ float  g_s[3 * B_TOT * CD];               // s1 | s2 | s3

// ---------------- f32x2 packed-math helpers (sm_103a) ----------------------
typedef unsigned long long ull;
__device__ __forceinline__ ull pack2(float lo, float hi) {
    ull r; asm("mov.b64 %0, {%1, %2};" : "=l"(r) : "f"(lo), "f"(hi)); return r;
}
__device__ __forceinline__ void unpack2(ull p, float& lo, float& hi) {
    asm("mov.b64 {%0, %1}, %2;" : "=f"(lo), "=f"(hi) : "l"(p));
}
__device__ __forceinline__ ull fma2(ull a, ull b, ull c) {
    ull d; asm("fma.rn.f32x2 %0, %1, %2, %3;" : "=l"(d) : "l"(a), "l"(b), "l"(c)); return d;
}
__device__ __forceinline__ ull add2(ull a, ull b) {
    ull d; asm("add.rn.f32x2 %0, %1, %2;" : "=l"(d) : "l"(a), "l"(b)); return d;
}

// ---------------- K1: u_hat = einsum('icdk,bik->bicd') + s1 partials -------
#define BT 32
#define IT 12
#define K1_THREADS 320
#define USTRIDE 100
#define K1_SMEM_FLOATS (BT*USTRIDE + IT*KD*CD)   // 18560 floats = 74.2 KB

__global__ void __launch_bounds__(K1_THREADS, 2)
k_uhat(const float* __restrict__ u, const float* __restrict__ W) {
    extern __shared__ float sm[];
    float* u_s = sm;                    // [BT][USTRIDE]
    float* w_s = sm + BT * USTRIDE;     // [IT][8][160]

    const int tid = threadIdx.x;
    const int b0  = blockIdx.x * BT;
    const int i0  = blockIdx.y * IT;

    for (int idx = tid; idx < BT * IT * KD; idx += K1_THREADS) {
        int bl = idx / (IT * KD);
        int r  = idx - bl * (IT * KD);
        u_s[bl * USTRIDE + r] =
            u[(size_t)(b0 + bl) * (IC * KD) + (size_t)i0 * KD + r];
    }
    for (int row = tid; row < IT * CD; row += K1_THREADS) {
        int il = row / CD, cd = row - il * CD;
        const float4 wa = *(const float4*)&W[((size_t)(i0 + il) * CD + cd) * KD];
        const float4 wb = *(const float4*)&W[((size_t)(i0 + il) * CD + cd) * KD + 4];
        float* dst = &w_s[il * (KD * CD) + cd];
        dst[0*CD] = wa.x; dst[1*CD] = wa.y; dst[2*CD] = wa.z; dst[3*CD] = wa.w;
        dst[4*CD] = wb.x; dst[5*CD] = wb.y; dst[6*CD] = wb.z; dst[7*CD] = wb.w;
    }
    __syncthreads();

    const int bh  = tid & 7;
    const int cdq = tid >> 3;
    const int cd0 = cdq * 4;

    ull sacc01[4], sacc23[4];
#pragma unroll
    for (int x = 0; x < 4; x++) { sacc01[x] = 0ull; sacc23[x] = 0ull; }

#pragma unroll 1
    for (int il = 0; il < IT; il++) {
        ull wlo[8], whi[8];
#pragma unroll
        for (int k = 0; k < 8; k++) {
            const float4 wv = *(const float4*)&w_s[(il * KD + k) * CD + cd0];
            wlo[k] = pack2(wv.x, wv.y);
            whi[k] = pack2(wv.z, wv.w);
        }
        const int ig = i0 + il;
#pragma unroll
        for (int bb = 0; bb < 4; bb++) {
            const int bl = bb * 8 + bh;
            const float4 ua = *(const float4*)&u_s[bl * USTRIDE + il * KD];
            const float4 ub = *(const float4*)&u_s[bl * USTRIDE + il * KD + 4];
            ull a01 = 0ull, a23 = 0ull, p;
            p = pack2(ua.x, ua.x); a01 = fma2(wlo[0], p, a01); a23 = fma2(whi[0], p, a23);
            p = pack2(ua.y, ua.y); a01 = fma2(wlo[1], p, a01); a23 = fma2(whi[1], p, a23);
            p = pack2(ua.z, ua.z); a01 = fma2(wlo[2], p, a01); a23 = fma2(whi[2], p, a23);
            p = pack2(ua.w, ua.w); a01 = fma2(wlo[3], p, a01); a23 = fma2(whi[3], p, a23);
            p = pack2(ub.x, ub.x); a01 = fma2(wlo[4], p, a01); a23 = fma2(whi[4], p, a23);
            p = pack2(ub.y, ub.y); a01 = fma2(wlo[5], p, a01); a23 = fma2(whi[5], p, a23);
            p = pack2(ub.z, ub.z); a01 = fma2(wlo[6], p, a01); a23 = fma2(whi[6], p, a23);
            p = pack2(ub.w, ub.w); a01 = fma2(wlo[7], p, a01); a23 = fma2(whi[7], p, a23);
            sacc01[bb] = add2(sacc01[bb], a01);
            sacc23[bb] = add2(sacc23[bb], a23);
            float f0, f1, f2, f3;
            unpack2(a01, f0, f1); unpack2(a23, f2, f3);
            __half2 pa = __floats2half2_rn(f0, f1);
            __half2 pb = __floats2half2_rn(f2, f3);
            ull payload = ((ull)*reinterpret_cast<unsigned*>(&pb) << 32)
                        |  (ull)*reinterpret_cast<unsigned*>(&pa);
            __half* dst = &g_uhat[((size_t)(b0 + bl) * IC + ig) * CD + cd0];
            asm volatile("st.global.cs.b64 [%0], %1;" :: "l"(dst), "l"(payload) : "memory");
        }
    }
#pragma unroll
    for (int bb = 0; bb < 4; bb++) {
        float f0, f1, f2, f3;
        unpack2(sacc01[bb], f0, f1); unpack2(sacc23[bb], f2, f3);
        float* so = &g_s[(b0 + bb * 8 + bh) * CD + cd0];
        atomicAdd(&so[0], f0); atomicAdd(&so[1], f1);
        atomicAdd(&so[2], f2); atomicAdd(&so[3], f3);
    }
}

// ---------------- final squash ----------------------------------------------
__global__ void k_squash(const float* __restrict__ s, float* __restrict__ v) {
    const int idx = blockIdx.x * blockDim.x + threadIdx.x;   // (b, c)
    if (idx >= B_TOT * NC) return;
    float vals[16];
    const float4* s4 = (const float4*)(s + (size_t)idx * 16);
    float n2 = 0.f;
#pragma unroll
    for (int q = 0; q < 4; q++) {
        float4 t = s4[q];
        vals[4*q+0] = t.x; vals[4*q+1] = t.y; vals[4*q+2] = t.z; vals[4*q+3] = t.w;
        n2 += t.x*t.x + t.y*t.y + t.z*t.z + t.w*t.w;
    }
    const float f = (n2 / (1.f + n2)) / (sqrtf(n2) + 1e-8f);
    float4* v4 = (float4*)(v + (size_t)idx * 16);
#pragma unroll
    for (int q = 0; q < 4; q++)
        v4[q] = make_float4(f*vals[4*q], f*vals[4*q+1], f*vals[4*q+2], f*vals[4*q+3]);
}

// ---------------- routing pass: cp.async smem pipeline ----------------------
__device__ __forceinline__ float ex2a(float x) { float y; asm("ex2.approx.f32 %0, %1;" : "=f"(y) : "f"(x)); return y; }
__device__ __forceinline__ float rcpa(float x) { float y; asm("rcp.approx.f32 %0, %1;" : "=f"(y) : "f"(x)); return y; }
__device__ __forceinline__ void cp_async16(void* smem, const void* gmem) {
    unsigned s = (unsigned)__cvta_generic_to_shared(smem);
    asm volatile("cp.async.cg.shared.global [%0], [%1], 16;" :: "r"(s), "l"(gmem) : "memory");
}
__device__ __forceinline__ void cp_commit() {
    asm volatile("cp.async.commit_group;" ::: "memory");
}
__device__ __forceinline__ void cp_wait3() {
    asm volatile("cp.async.wait_group 3;" ::: "memory");
}

#define NSPL 4
#define RT_THREADS 256
#define TI 32                    // i per stage
#define DST 4                    // pipeline depth
#define STAGE_BYTES (TI * CD * 2)   // 10240

template <int MODE>   // 1: v1 only, 2: v1+v2 combined
__global__ void __launch_bounds__(RT_THREADS)
k_route(const float* __restrict__ s_in1, const float* __restrict__ s_in2,
        float* __restrict__ s_out) {
    __shared__ __align__(16) char tiles[DST][STAGE_BYTES];
    __shared__ float4 vcs[40];

    const int b      = blockIdx.x;
    const int isplit = blockIdx.y;
    const int tid  = threadIdx.x;
    const int warp = tid >> 5, lane = tid & 31;
    const int grp = lane >> 3, sub = lane & 7;

    const int i0 = isplit * (IC / NSPL);
    const __half* gsrc = g_uhat + ((size_t)b * IC + i0) * CD;
    const int T = (IC / NSPL) / TI;        // 9 stages

    // combined coupling vector: vc = v1 (+ v2)
    if (tid < 10) {
        float vc[16]; float n2 = 0.f;
#pragma unroll
        for (int d = 0; d < 16; d++) {
            vc[d] = s_in1[(size_t)b * CD + tid * 16 + d] * 0.1f;
            n2 += vc[d] * vc[d];
        }
        const float fa = (n2 / (1.f + n2)) / (sqrtf(n2) + 1e-8f);
#pragma unroll
        for (int d = 0; d < 16; d++) vc[d] *= fa;
        if (MODE == 2) {
            float vb[16]; float m2 = 0.f;
#pragma unroll
            for (int d = 0; d < 16; d++) {
                vb[d] = s_in2[(size_t)b * CD + tid * 16 + d];
                m2 += vb[d] * vb[d];
            }
            const float fb = (m2 / (1.f + m2)) / (sqrtf(m2) + 1e-8f);
#pragma unroll
            for (int d = 0; d < 16; d++) vc[d] += fb * vb[d];
        }
#pragma unroll
        for (int q = 0; q < 4; q++)
            vcs[tid * 4 + q] = make_float4(vc[4*q], vc[4*q+1], vc[4*q+2], vc[4*q+3]);
    }

    // pipeline prologue: stages 0..DST-2
#pragma unroll
    for (int s = 0; s < DST - 1; s++) {
        const char* src = (const char*)(gsrc + (size_t)s * TI * CD);
        char* dst = tiles[s];
        for (int k = tid; k < STAGE_BYTES / 16; k += RT_THREADS)
            cp_async16(dst + k * 16, src + k * 16);
        cp_commit();
    }
    __syncthreads();   // vcs ready

    float4 vr[5];
#pragma unroll
    for (int j = 0; j < 5; j++) vr[j] = vcs[sub + 8 * j];
    float4 sacc[5];
#pragma unroll
    for (int j = 0; j < 5; j++) sacc[j] = make_float4(0.f, 0.f, 0.f, 0.f);

    const int il = warp * 4 + grp;   // this lane's i within each stage

#pragma unroll 1
    for (int t = 0; t < T; t++) {
        if (t + DST - 1 < T) {
            const int s = t + DST - 1;
            const char* src = (const char*)(gsrc + (size_t)s * TI * CD);
            char* dst = tiles[s & (DST - 1)];
            for (int k = tid; k < STAGE_BYTES / 16; k += RT_THREADS)
                cp_async16(dst + k * 16, src + k * 16);
        }
        cp_commit();
        cp_wait3();          // stage t complete
        __syncthreads();

        const uint2* row = (const uint2*)(tiles[t & (DST - 1)] + il * (CD * 2));
        uint2 q[5];
#pragma unroll
        for (int j = 0; j < 5; j++) q[j] = row[sub + 8 * j];
        float4 uh[5];
        float e[5]; float esum = 0.f;
#pragma unroll
        for (int j = 0; j < 5; j++) {
            float2 f0 = __half22float2(*reinterpret_cast<const __half2*>(&q[j].x));
            float2 f1 = __half22float2(*reinterpret_cast<const __half2*>(&q[j].y));
            uh[j] = make_float4(f0.x, f0.y, f1.x, f1.y);
            float d = uh[j].x * vr[j].x + uh[j].y * vr[j].y
                    + uh[j].z * vr[j].z + uh[j].w * vr[j].w;
            d += __shfl_xor_sync(0xffffffffu, d, 1);
            d += __shfl_xor_sync(0xffffffffu, d, 2);
            e[j] = ex2a(d * 1.4426950408889634f);   // class 2j + (sub>=4)
            esum += e[j];
        }
        const float tot = esum + __shfl_xor_sync(0xffffffffu, esum, 4);
        const float r = rcpa(tot);
#pragma unroll
        for (int j = 0; j < 5; j++) {
            const float cw = e[j] * r;
            sacc[j].x += cw * uh[j].x; sacc[j].y += cw * uh[j].y;
            sacc[j].z += cw * uh[j].z; sacc[j].w += cw * uh[j].w;
        }
        __syncthreads();     // all warps done with slot before it is refilled
    }

    float* so = s_out + (size_t)b * CD;
#pragma unroll
    for (int j = 0; j < 5; j++) {
        const int cdb = 4 * (sub + 8 * j);
        atomicAdd(&so[cdb + 0], sacc[j].x);
        atomicAdd(&so[cdb + 1], sacc[j].y);
        atomicAdd(&so[cdb + 2], sacc[j].z);
        atomicAdd(&so[cdb + 3], sacc[j].w);
    }
}

// ---------------- launch -----------------------------------------------------
extern "C" void kernel_launch(void* const* d_in, const int* in_sizes, int n_in,
                              void* d_out, int out_size) {
    const float* u = (const float*)d_in[0];
    const float* W = (const float*)d_in[1];
    if (n_in >= 2 && in_sizes[0] == IC * CD * KD) {   // swap safety
        const float* t = u; u = W; W = t;
    }

    cudaFuncSetAttribute(k_uhat, cudaFuncAttributeMaxDynamicSharedMemorySize,
                         K1_SMEM_FLOATS * (int)sizeof(float));

    void* ps;
    cudaGetSymbolAddress(&ps, g_s);
    float* s1 = (float*)ps;
    float* s2 = s1 + B_TOT * CD;
    float* s3 = s2 + B_TOT * CD;

    cudaMemsetAsync(ps, 0, 3 * B_TOT * CD * sizeof(float), 0);

    // 1) u_hat (fp16) + raw sum over i (iter-0 coupling coeffs are exactly 0.1)
    k_uhat<<<dim3(B_TOT / BT, IC / IT), K1_THREADS,
             K1_SMEM_FLOATS * sizeof(float)>>>(u, W);

    // 2) iter-1: v1 = squash(0.1*s1); logits = <uhat, v1>; s2
    k_route<1><<<dim3(B_TOT, NSPL), RT_THREADS>>>(s1, s1, s2);
    // 3) iter-2: vc = v1 + v2; logits = <uhat, vc>; s3
    k_route<2><<<dim3(B_TOT, NSPL), RT_THREADS>>>(s1, s2, s3);
    // 4) output v = squash(s3)
    const int sq_blocks = (B_TOT * NC + 255) / 256;
    k_squash<<<sq_blocks, 256>>>(s3, (float*)d_out);
}

// round 8
// speedup vs baseline: 2.4374x; 1.2908x over previous
#include <cuda_runtime.h>
#include <cuda_fp16.h>
#include <cstdint>
#include <cstddef>

#define B_TOT 512
#define IC    1152
#define CD    160
#define KD    8
#define NC    10

// ---------------- scratch (device globals; no runtime allocation) ----------
__device__ __half g_uhat[(size_t)B_TOT * IC * CD];   // 188 MB, fp16
__device__ float  g_s[3 * B_TOT * CD];               // s1 | s2 | s3

// ---------------- f32x2 packed-math helpers (sm_103a) ----------------------
typedef unsigned long long ull;
__device__ __forceinline__ ull pack2(float lo, float hi) {
    ull r; asm("mov.b64 %0, {%1, %2};" : "=l"(r) : "f"(lo), "f"(hi)); return r;
}
__device__ __forceinline__ void unpack2(ull p, float& lo, float& hi) {
    asm("mov.b64 {%0, %1}, %2;" : "=f"(lo), "=f"(hi) : "l"(p));
}
__device__ __forceinline__ ull fma2(ull a, ull b, ull c) {
    ull d; asm("fma.rn.f32x2 %0, %1, %2, %3;" : "=l"(d) : "l"(a), "l"(b), "l"(c)); return d;
}
__device__ __forceinline__ ull add2(ull a, ull b) {
    ull d; asm("add.rn.f32x2 %0, %1, %2;" : "=l"(d) : "l"(a), "l"(b)); return d;
}

// ---------------- K1: u_hat = einsum('icdk,bik->bicd') + s1 partials -------
#define BT 32
#define IT 12
#define K1_THREADS 320
#define USTRIDE 100
#define K1_SMEM_FLOATS (BT*USTRIDE + IT*KD*CD)   // 18560 floats = 74.2 KB

__global__ void __launch_bounds__(K1_THREADS, 2)
k_uhat(const float* __restrict__ u, const float* __restrict__ W) {
    extern __shared__ float sm[];
    float* u_s = sm;                    // [BT][USTRIDE]
    float* w_s = sm + BT * USTRIDE;     // [IT][8][160]

    const int tid = threadIdx.x;
    const int b0  = blockIdx.x * BT;
    const int i0  = blockIdx.y * IT;

    for (int idx = tid; idx < BT * IT * KD; idx += K1_THREADS) {
        int bl = idx / (IT * KD);
        int r  = idx - bl * (IT * KD);
        u_s[bl * USTRIDE + r] =
            u[(size_t)(b0 + bl) * (IC * KD) + (size_t)i0 * KD + r];
    }
    for (int row = tid; row < IT * CD; row += K1_THREADS) {
        int il = row / CD, cd = row - il * CD;
        const float4 wa = *(const float4*)&W[((size_t)(i0 + il) * CD + cd) * KD];
        const float4 wb = *(const float4*)&W[((size_t)(i0 + il) * CD + cd) * KD + 4];
        float* dst = &w_s[il * (KD * CD) + cd];
        dst[0*CD] = wa.x; dst[1*CD] = wa.y; dst[2*CD] = wa.z; dst[3*CD] = wa.w;
        dst[4*CD] = wb.x; dst[5*CD] = wb.y; dst[6*CD] = wb.z; dst[7*CD] = wb.w;
    }
    __syncthreads();

    const int bh  = tid & 7;
    const int cdq = tid >> 3;
    const int cd0 = cdq * 4;

    ull sacc01[4], sacc23[4];
#pragma unroll
    for (int x = 0; x < 4; x++) { sacc01[x] = 0ull; sacc23[x] = 0ull; }

#pragma unroll 1
    for (int il = 0; il < IT; il++) {
        ull wlo[8], whi[8];
#pragma unroll
        for (int k = 0; k < 8; k++) {
            const float4 wv = *(const float4*)&w_s[(il * KD + k) * CD + cd0];
            wlo[k] = pack2(wv.x, wv.y);
            whi[k] = pack2(wv.z, wv.w);
        }
        const int ig = i0 + il;
#pragma unroll
        for (int bb = 0; bb < 4; bb++) {
            const int bl = bb * 8 + bh;
            const float4 ua = *(const float4*)&u_s[bl * USTRIDE + il * KD];
            const float4 ub = *(const float4*)&u_s[bl * USTRIDE + il * KD + 4];
            ull a01 = 0ull, a23 = 0ull, p;
            p = pack2(ua.x, ua.x); a01 = fma2(wlo[0], p, a01); a23 = fma2(whi[0], p, a23);
            p = pack2(ua.y, ua.y); a01 = fma2(wlo[1], p, a01); a23 = fma2(whi[1], p, a23);
            p = pack2(ua.z, ua.z); a01 = fma2(wlo[2], p, a01); a23 = fma2(whi[2], p, a23);
            p = pack2(ua.w, ua.w); a01 = fma2(wlo[3], p, a01); a23 = fma2(whi[3], p, a23);
            p = pack2(ub.x, ub.x); a01 = fma2(wlo[4], p, a01); a23 = fma2(whi[4], p, a23);
            p = pack2(ub.y, ub.y); a01 = fma2(wlo[5], p, a01); a23 = fma2(whi[5], p, a23);
            p = pack2(ub.z, ub.z); a01 = fma2(wlo[6], p, a01); a23 = fma2(whi[6], p, a23);
            p = pack2(ub.w, ub.w); a01 = fma2(wlo[7], p, a01); a23 = fma2(whi[7], p, a23);
            sacc01[bb] = add2(sacc01[bb], a01);
            sacc23[bb] = add2(sacc23[bb], a23);
            float f0, f1, f2, f3;
            unpack2(a01, f0, f1); unpack2(a23, f2, f3);
            __half2 pa = __floats2half2_rn(f0, f1);
            __half2 pb = __floats2half2_rn(f2, f3);
            ull payload = ((ull)*reinterpret_cast<unsigned*>(&pb) << 32)
                        |  (ull)*reinterpret_cast<unsigned*>(&pa);
            __half* dst = &g_uhat[((size_t)(b0 + bl) * IC + ig) * CD + cd0];
            asm volatile("st.global.cs.b64 [%0], %1;" :: "l"(dst), "l"(payload) : "memory");
        }
    }
#pragma unroll
    for (int bb = 0; bb < 4; bb++) {
        float f0, f1, f2, f3;
        unpack2(sacc01[bb], f0, f1); unpack2(sacc23[bb], f2, f3);
        float* so = &g_s[(b0 + bb * 8 + bh) * CD + cd0];
        atomicAdd(&so[0], f0); atomicAdd(&so[1], f1);
        atomicAdd(&so[2], f2); atomicAdd(&so[3], f3);
    }
}

// ---------------- final squash ----------------------------------------------
__global__ void k_squash(const float* __restrict__ s, float* __restrict__ v) {
    const int idx = blockIdx.x * blockDim.x + threadIdx.x;   // (b, c)
    if (idx >= B_TOT * NC) return;
    float vals[16];
    const float4* s4 = (const float4*)(s + (size_t)idx * 16);
    float n2 = 0.f;
#pragma unroll
    for (int q = 0; q < 4; q++) {
        float4 t = s4[q];
        vals[4*q+0] = t.x; vals[4*q+1] = t.y; vals[4*q+2] = t.z; vals[4*q+3] = t.w;
        n2 += t.x*t.x + t.y*t.y + t.z*t.z + t.w*t.w;
    }
    const float f = (n2 / (1.f + n2)) / (sqrtf(n2) + 1e-8f);
    float4* v4 = (float4*)(v + (size_t)idx * 16);
#pragma unroll
    for (int q = 0; q < 4; q++)
        v4[q] = make_float4(f*vals[4*q], f*vals[4*q+1], f*vals[4*q+2], f*vals[4*q+3]);
}

// ---------------- routing pass (fp16 u_hat, hierarchical reduction) ---------
__device__ __forceinline__ float ex2a(float x) { float y; asm("ex2.approx.f32 %0, %1;" : "=f"(y) : "f"(x)); return y; }
__device__ __forceinline__ float rcpa(float x) { float y; asm("rcp.approx.f32 %0, %1;" : "=f"(y) : "f"(x)); return y; }

#define NSPL 4
#define RT_THREADS 256

template <int MODE>   // 1: v1 only, 2: v1+v2 combined
__global__ void __launch_bounds__(RT_THREADS)
k_route(const float* __restrict__ s_in1, const float* __restrict__ s_in2,
        float* __restrict__ s_out) {
    __shared__ float4 vcs[40];
    __shared__ float  ssum[CD];

    const int b      = blockIdx.x;
    const int isplit = blockIdx.y;
    const int tid  = threadIdx.x;
    const int warp = tid >> 5, lane = tid & 31;
    const int grp = lane >> 3, sub = lane & 7;

    if (tid < CD) ssum[tid] = 0.f;

    // combined coupling vector: vc = v1 (+ v2)
    if (tid < 10) {
        float vc[16]; float n2 = 0.f;
#pragma unroll
        for (int d = 0; d < 16; d++) {
            vc[d] = s_in1[(size_t)b * CD + tid * 16 + d] * 0.1f;
            n2 += vc[d] * vc[d];
        }
        const float fa = (n2 / (1.f + n2)) / (sqrtf(n2) + 1e-8f);
#pragma unroll
        for (int d = 0; d < 16; d++) vc[d] *= fa;
        if (MODE == 2) {
            float vb[16]; float m2 = 0.f;
#pragma unroll
            for (int d = 0; d < 16; d++) {
                vb[d] = s_in2[(size_t)b * CD + tid * 16 + d];
                m2 += vb[d] * vb[d];
            }
            const float fb = (m2 / (1.f + m2)) / (sqrtf(m2) + 1e-8f);
#pragma unroll
            for (int d = 0; d < 16; d++) vc[d] += fb * vb[d];
        }
#pragma unroll
        for (int q = 0; q < 4; q++)
            vcs[tid * 4 + q] = make_float4(vc[4*q], vc[4*q+1], vc[4*q+2], vc[4*q+3]);
    }
    __syncthreads();

    const uint2* uh_2 = (const uint2*)g_uhat;

    float4 vr[5];
#pragma unroll
    for (int j = 0; j < 5; j++) vr[j] = vcs[sub + 8 * j];

    float4 sacc[5];
#pragma unroll
    for (int j = 0; j < 5; j++) sacc[j] = make_float4(0.f, 0.f, 0.f, 0.f);

    const int iper = IC / NSPL;          // 288;  9 rounds of 32 i
#pragma unroll 3
    for (int t = 0; t < iper / 32; t++) {
        const int i = isplit * iper + t * 32 + warp * 4 + grp;
        const size_t base = (size_t)(b * IC + i) * 40;
        uint2 q[5];
#pragma unroll
        for (int j = 0; j < 5; j++) q[j] = __ldcs(&uh_2[base + sub + 8 * j]);
        float4 uh[5];
        float e[5]; float esum = 0.f;
#pragma unroll
        for (int j = 0; j < 5; j++) {
            float2 f0 = __half22float2(*reinterpret_cast<const __half2*>(&q[j].x));
            float2 f1 = __half22float2(*reinterpret_cast<const __half2*>(&q[j].y));
            uh[j] = make_float4(f0.x, f0.y, f1.x, f1.y);
            float d = uh[j].x * vr[j].x + uh[j].y * vr[j].y
                    + uh[j].z * vr[j].z + uh[j].w * vr[j].w;
            d += __shfl_xor_sync(0xffffffffu, d, 1);
            d += __shfl_xor_sync(0xffffffffu, d, 2);
            e[j] = ex2a(d * 1.4426950408889634f);   // class 2j + (sub>=4)
            esum += e[j];
        }
        const float tot = esum + __shfl_xor_sync(0xffffffffu, esum, 4);
        const float r = rcpa(tot);
#pragma unroll
        for (int j = 0; j < 5; j++) {
            const float cw = e[j] * r;
            sacc[j].x += cw * uh[j].x; sacc[j].y += cw * uh[j].y;
            sacc[j].z += cw * uh[j].z; sacc[j].w += cw * uh[j].w;
        }
    }

    // ---- hierarchical reduction: warp (over grp) -> smem -> 160 global atomics
#pragma unroll
    for (int j = 0; j < 5; j++) {
        sacc[j].x += __shfl_xor_sync(0xffffffffu, sacc[j].x, 8);
        sacc[j].x += __shfl_xor_sync(0xffffffffu, sacc[j].x, 16);
        sacc[j].y += __shfl_xor_sync(0xffffffffu, sacc[j].y, 8);
        sacc[j].y += __shfl_xor_sync(0xffffffffu, sacc[j].y, 16);
        sacc[j].z += __shfl_xor_sync(0xffffffffu, sacc[j].z, 8);
        sacc[j].z += __shfl_xor_sync(0xffffffffu, sacc[j].z, 16);
        sacc[j].w += __shfl_xor_sync(0xffffffffu, sacc[j].w, 8);
        sacc[j].w += __shfl_xor_sync(0xffffffffu, sacc[j].w, 16);
    }
    if (grp == 0) {
#pragma unroll
        for (int j = 0; j < 5; j++) {
            const int cdb = 4 * (sub + 8 * j);
            atomicAdd(&ssum[cdb + 0], sacc[j].x);
            atomicAdd(&ssum[cdb + 1], sacc[j].y);
            atomicAdd(&ssum[cdb + 2], sacc[j].z);
            atomicAdd(&ssum[cdb + 3], sacc[j].w);
        }
    }
    __syncthreads();
    if (tid < CD)
        atomicAdd(&s_out[(size_t)b * CD + tid], ssum[tid]);
}

// ---------------- launch -----------------------------------------------------
extern "C" void kernel_launch(void* const* d_in, const int* in_sizes, int n_in,
                              void* d_out, int out_size) {
    const float* u = (const float*)d_in[0];
    const float* W = (const float*)d_in[1];
    if (n_in >= 2 && in_sizes[0] == IC * CD * KD) {   // swap safety
        const float* t = u; u = W; W = t;
    }

    cudaFuncSetAttribute(k_uhat, cudaFuncAttributeMaxDynamicSharedMemorySize,
                         K1_SMEM_FLOATS * (int)sizeof(float));

    void* ps;
    cudaGetSymbolAddress(&ps, g_s);
    float* s1 = (float*)ps;
    float* s2 = s1 + B_TOT * CD;
    float* s3 = s2 + B_TOT * CD;

    cudaMemsetAsync(ps, 0, 3 * B_TOT * CD * sizeof(float), 0);

    // 1) u_hat (fp16) + raw sum over i (iter-0 coupling coeffs are exactly 0.1)
    k_uhat<<<dim3(B_TOT / BT, IC / IT), K1_THREADS,
             K1_SMEM_FLOATS * sizeof(float)>>>(u, W);

    // 2) iter-1: v1 = squash(0.1*s1); logits = <uhat, v1>; s2
    k_route<1><<<dim3(B_TOT, NSPL), RT_THREADS>>>(s1, s1, s2);
    // 3) iter-2: vc = v1 + v2; logits = <uhat, vc>; s3
    k_route<2><<<dim3(B_TOT, NSPL), RT_THREADS>>>(s1, s2, s3);
    // 4) output v = squash(s3)
    const int sq_blocks = (B_TOT * NC + 255) / 256;
    k_squash<<<sq_blocks, 256>>>(s3, (float*)d_out);
}